// round 2
// baseline (speedup 1.0000x reference)
#include <cuda_runtime.h>

#define NODES_MAX 100000
#define EDGES_MAX 1000000
#define HID 64

// Scratch (allocation-free rule: __device__ globals)
__device__ float g_dinv[NODES_MAX];
__device__ float g_norm[EDGES_MAX];
__device__ float g_h  [(size_t)NODES_MAX * HID];
__device__ float g_mid[(size_t)NODES_MAX * HID];
__device__ float g_h2 [(size_t)NODES_MAX * HID];

__global__ void k_init_deg(float* deg, int n) {
    int i = blockIdx.x * blockDim.x + threadIdx.x;
    if (i < n) deg[i] = 1.0f;   // self-loop weight
}

__global__ void k_deg_accum(const int* __restrict__ dst, const float* __restrict__ ew,
                            float* deg, int ne) {
    int i = blockIdx.x * blockDim.x + threadIdx.x;
    if (i < ne) atomicAdd(&deg[dst[i]], ew[i]);
}

__global__ void k_dinv(float* deg, int n) {
    int i = blockIdx.x * blockDim.x + threadIdx.x;
    if (i < n) {
        float d = deg[i];
        deg[i] = (d > 0.f) ? rsqrtf(d) : 0.f;
    }
}

__global__ void k_norm(const int* __restrict__ src, const int* __restrict__ dst,
                       const float* __restrict__ ew, const float* __restrict__ dinv,
                       float* __restrict__ nrm, int ne) {
    int i = blockIdx.x * blockDim.x + threadIdx.x;
    if (i < ne) nrm[i] = dinv[src[i]] * ew[i] * dinv[dst[i]];
}

// Y[n,64] = (RELU? max(X,0) : X)[n,64] @ W[64,64]
template<bool RELU>
__global__ void k_gemm64(const float* __restrict__ X, const float* __restrict__ W,
                         float* __restrict__ Y, int n) {
    __shared__ float sW[HID * HID];     // 16 KB
    __shared__ float sX[32 * HID];      // 8 KB
    int tid = threadIdx.x;
    #pragma unroll
    for (int j = 0; j < 16; j++) sW[tid + j * 256] = W[tid + j * 256];

    int row0 = blockIdx.x * 32;
    #pragma unroll
    for (int j = 0; j < 8; j++) {
        int idx = tid + j * 256;
        int r = idx >> 6, c = idx & 63;
        float v = (row0 + r < n) ? X[(size_t)(row0 + r) * HID + c] : 0.f;
        if (RELU) v = fmaxf(v, 0.f);
        sX[idx] = v;
    }
    __syncthreads();

    int c  = tid & 63;
    int rb = tid >> 6;                  // 0..3
    float acc[8];
    #pragma unroll
    for (int rr = 0; rr < 8; rr++) acc[rr] = 0.f;
    #pragma unroll
    for (int k = 0; k < HID; k++) {
        float w = sW[k * HID + c];      // conflict-free: consecutive c per warp
        #pragma unroll
        for (int rr = 0; rr < 8; rr++)
            acc[rr] += sX[(rb * 8 + rr) * HID + k] * w;   // broadcast
    }
    #pragma unroll
    for (int rr = 0; rr < 8; rr++) {
        int r = row0 + rb * 8 + rr;
        if (r < n) Y[(size_t)r * HID + c] = acc[rr];
    }
}

// out[i] = b + h[i] * dinv[i]^2   (self-loop message + bias; initializes out)
__global__ void k_self_bias(const float* __restrict__ h, const float* __restrict__ dinv,
                            const float* __restrict__ b, float* __restrict__ out, int n) {
    int idx = blockIdx.x * blockDim.x + threadIdx.x;
    int node = idx >> 4, q = idx & 15;
    if (node >= n) return;
    float s = dinv[node]; s = s * s;
    float4 hv = *(const float4*)(h + (size_t)node * HID + (q << 2));
    float4 bv = __ldg((const float4*)(b + (q << 2)));
    float4 o;
    o.x = bv.x + hv.x * s;
    o.y = bv.y + hv.y * s;
    o.z = bv.z + hv.z * s;
    o.w = bv.w + hv.w * s;
    *(float4*)(out + (size_t)node * HID + (q << 2)) = o;
}

// out[dst] += norm * h[src]; 16 lanes per edge, float4 per lane, vector REDG
__global__ void k_scatter(const float* __restrict__ h, const float* __restrict__ nrm,
                          const int* __restrict__ src, const int* __restrict__ dst,
                          float* out, int ne) {
    int idx = blockIdx.x * blockDim.x + threadIdx.x;
    int e = idx >> 4, q = idx & 15;
    if (e >= ne) return;
    int s = __ldg(src + e);
    int d = __ldg(dst + e);
    float w = __ldg(nrm + e);
    float4 v = __ldg((const float4*)(h + (size_t)s * HID + (q << 2)));
    float* p = out + (size_t)d * HID + (q << 2);
    asm volatile("red.global.add.v4.f32 [%0], {%1, %2, %3, %4};"
                 :: "l"(p), "f"(v.x * w), "f"(v.y * w), "f"(v.z * w), "f"(v.w * w)
                 : "memory");
}

extern "C" void kernel_launch(void* const* d_in, const int* in_sizes, int n_in,
                              void* d_out, int out_size) {
    const float* x  = (const float*)d_in[0];
    const int*   ei = (const int*)  d_in[1];
    const float* ew = (const float*)d_in[2];
    const float* W1 = (const float*)d_in[3];
    const float* b1 = (const float*)d_in[4];
    const float* W2 = (const float*)d_in[5];
    const float* b2 = (const float*)d_in[6];
    float* out = (float*)d_out;

    int n  = in_sizes[0] / HID;
    int ne = in_sizes[2];
    const int* src = ei;
    const int* dst = ei + ne;

    float *dinv, *nrm, *h, *mid, *h2;
    cudaGetSymbolAddress((void**)&dinv, g_dinv);
    cudaGetSymbolAddress((void**)&nrm,  g_norm);
    cudaGetSymbolAddress((void**)&h,    g_h);
    cudaGetSymbolAddress((void**)&mid,  g_mid);
    cudaGetSymbolAddress((void**)&h2,   g_h2);

    const int T = 256;
    int gn  = (n + T - 1) / T;
    int ge  = (ne + T - 1) / T;
    int gs  = (int)(((size_t)ne * 16 + T - 1) / T);
    int gsb = (int)(((size_t)n * 16 + T - 1) / T);
    int gg  = (n + 31) / 32;

    // shared normalization (same for both layers)
    k_init_deg <<<gn, T>>>(dinv, n);
    k_deg_accum<<<ge, T>>>(dst, ew, dinv, ne);
    k_dinv     <<<gn, T>>>(dinv, n);
    k_norm     <<<ge, T>>>(src, dst, ew, dinv, nrm, ne);

    // layer 1: mid = relu-input for layer 2 (relu applied on load in next gemm)
    k_gemm64<false><<<gg, 256>>>(x, W1, h, n);
    k_self_bias<<<gsb, T>>>(h, dinv, b1, mid, n);
    k_scatter  <<<gs,  T>>>(h, nrm, src, dst, mid, ne);

    // layer 2
    k_gemm64<true><<<gg, 256>>>(mid, W2, h2, n);
    k_self_bias<<<gsb, T>>>(h2, dinv, b2, out, n);
    k_scatter  <<<gs,  T>>>(h2, nrm, src, dst, out, ne);
}

// round 4
// speedup vs baseline: 1.4801x; 1.4801x over previous
#include <cuda_runtime.h>

#define NODES_MAX 100000
#define EDGES_MAX 1000000
#define HID 64

// Scratch (allocation-free rule: __device__ globals)
__device__ float g_dinv[NODES_MAX];
__device__ int   g_cnt [NODES_MAX];
__device__ int   g_off [NODES_MAX];
__device__ int   g_cur [NODES_MAX];
__device__ int   g_bsum[256];
__device__ int2  g_csr [EDGES_MAX];
__device__ float g_h  [(size_t)NODES_MAX * HID];
__device__ float g_mid[(size_t)NODES_MAX * HID];
__device__ float g_h2 [(size_t)NODES_MAX * HID];

#define FMA_F32X2(d, a, b) \
    asm("fma.rn.f32x2 %0, %1, %2, %0;" : "+l"(d) : "l"(a), "l"(b))
#define PACK_F32X2(out, lo, hi) \
    asm("mov.b64 %0, {%1, %2};" : "=l"(out) : "f"(lo), "f"(hi))
#define UNPACK_F32X2(lo, hi, in) \
    asm("mov.b64 {%0, %1}, %2;" : "=f"(lo), "=f"(hi) : "l"(in))

// ---------------------------------------------------------------- prep
__global__ void k_init(float* deg, int* cnt, int n) {
    int i = blockIdx.x * blockDim.x + threadIdx.x;
    if (i < n) { deg[i] = 1.0f; cnt[i] = 0; }   // self-loop weight, zero hist
}

__global__ void k_hist(const int* __restrict__ dst, const float* __restrict__ ew,
                       float* deg, int* cnt, int ne) {
    int i = blockIdx.x * blockDim.x + threadIdx.x;
    if (i < ne) {
        int d = dst[i];
        atomicAdd(&deg[d], ew[i]);
        atomicAdd(&cnt[d], 1);
    }
}

__global__ void k_dinv(float* deg, int n) {
    int i = blockIdx.x * blockDim.x + threadIdx.x;
    if (i < n) {
        float d = deg[i];
        deg[i] = (d > 0.f) ? rsqrtf(d) : 0.f;
    }
}

// 3-kernel exclusive scan of cnt -> off
__global__ void k_scan1(const int* __restrict__ cnt, int* __restrict__ off,
                        int* __restrict__ bsum, int n) {
    __shared__ int ws[32];
    int i = blockIdx.x * 1024 + threadIdx.x;
    int lane = threadIdx.x & 31, w = threadIdx.x >> 5;
    int v = (i < n) ? cnt[i] : 0;
    int incl = v;
    #pragma unroll
    for (int d = 1; d < 32; d <<= 1) {
        int t = __shfl_up_sync(0xffffffffu, incl, d);
        if (lane >= d) incl += t;
    }
    if (lane == 31) ws[w] = incl;
    __syncthreads();
    if (w == 0) {
        int x = ws[lane];
        #pragma unroll
        for (int d = 1; d < 32; d <<= 1) {
            int t = __shfl_up_sync(0xffffffffu, x, d);
            if (lane >= d) x += t;
        }
        ws[lane] = x;
    }
    __syncthreads();
    int wpre = (w == 0) ? 0 : ws[w - 1];
    if (i < n) off[i] = wpre + incl - v;
    if (threadIdx.x == 1023) bsum[blockIdx.x] = ws[31];
}

__global__ void k_scan2(int* bsum, int nb) {
    __shared__ int s[256];
    int t = threadIdx.x;
    s[t] = (t < nb) ? bsum[t] : 0;
    __syncthreads();
    #pragma unroll
    for (int d = 1; d < 256; d <<= 1) {
        int v = (t >= d) ? s[t - d] : 0;
        __syncthreads();
        s[t] += v;
        __syncthreads();
    }
    if (t < nb) bsum[t] = (t == 0) ? 0 : s[t - 1];
}

__global__ void k_scan3(int* __restrict__ off, int* __restrict__ cur,
                        const int* __restrict__ bsum, int n) {
    int i = blockIdx.x * blockDim.x + threadIdx.x;
    if (i < n) {
        int o = off[i] + bsum[i >> 10];
        off[i] = o;
        cur[i] = o;
    }
}

// place edges: csr[pos] = {src, dinv[src]*ew*dinv[dst]}
__global__ void k_place(const int* __restrict__ src, const int* __restrict__ dst,
                        const float* __restrict__ ew, const float* __restrict__ dinv,
                        int* cur, int2* __restrict__ csr, int ne) {
    int i = blockIdx.x * blockDim.x + threadIdx.x;
    if (i < ne) {
        int s = src[i], d = dst[i];
        int pos = atomicAdd(&cur[d], 1);
        float w = __ldg(dinv + s) * ew[i] * __ldg(dinv + d);
        csr[pos] = make_int2(s, __float_as_int(w));
    }
}

// ---------------------------------------------------------------- GEMM
// Y[n,64] = (RELU? max(X,0) : X) @ W[64,64]; 64 rows/block, 4x4 reg tile, f32x2 FMA
#define SX_STRIDE 68
template<bool RELU>
__global__ void __launch_bounds__(256) k_gemm64(const float* __restrict__ X,
                                                const float* __restrict__ W,
                                                float* __restrict__ Y, int n) {
    __shared__ float sW[HID * HID];          // 16 KB
    __shared__ float sX[HID * SX_STRIDE];    // 17 KB (padded)
    int tid = threadIdx.x;
    int row0 = blockIdx.x * 64;

    #pragma unroll
    for (int j = 0; j < 4; j++) {
        int vi = tid + j * 256;              // float4 index 0..1023
        float4 wv = __ldg((const float4*)W + vi);
        *(float4*)&sW[vi * 4] = wv;
    }
    #pragma unroll
    for (int j = 0; j < 4; j++) {
        int vi = tid + j * 256;
        int r = vi >> 4;                     // 16 float4 per row
        int c4 = (vi & 15) * 4;
        float4 xv = make_float4(0.f, 0.f, 0.f, 0.f);
        if (row0 + r < n) xv = __ldg((const float4*)(X + (size_t)(row0 + r) * HID + c4));
        if (RELU) {
            xv.x = fmaxf(xv.x, 0.f); xv.y = fmaxf(xv.y, 0.f);
            xv.z = fmaxf(xv.z, 0.f); xv.w = fmaxf(xv.w, 0.f);
        }
        *(float4*)&sX[r * SX_STRIDE + c4] = xv;
    }
    __syncthreads();

    int tx = tid & 15, ty = tid >> 4;
    int c0 = tx * 4, r0 = ty * 4;
    unsigned long long acc[4][2];
    #pragma unroll
    for (int i = 0; i < 4; i++) { acc[i][0] = 0ull; acc[i][1] = 0ull; }

    #pragma unroll 4
    for (int k = 0; k < HID; k++) {
        float4 wv = *(const float4*)&sW[k * HID + c0];
        unsigned long long w01, w23;
        PACK_F32X2(w01, wv.x, wv.y);
        PACK_F32X2(w23, wv.z, wv.w);
        #pragma unroll
        for (int i = 0; i < 4; i++) {
            float x = sX[(r0 + i) * SX_STRIDE + k];
            unsigned long long xp;
            PACK_F32X2(xp, x, x);
            FMA_F32X2(acc[i][0], xp, w01);
            FMA_F32X2(acc[i][1], xp, w23);
        }
    }

    #pragma unroll
    for (int i = 0; i < 4; i++) {
        int r = row0 + r0 + i;
        if (r < n) {
            float4 o;
            UNPACK_F32X2(o.x, o.y, acc[i][0]);
            UNPACK_F32X2(o.z, o.w, acc[i][1]);
            *(float4*)(Y + (size_t)r * HID + c0) = o;
        }
    }
}

// ---------------------------------------------------------------- gather
// out[i] = b + h[i]*dinv[i]^2 + sum_{edges into i} w * h[src]
__global__ void __launch_bounds__(256) k_gather(
    const float* __restrict__ h, const int2* __restrict__ csr,
    const int* __restrict__ off, const int* __restrict__ cnt,
    const float* __restrict__ dinv, const float* __restrict__ b,
    float* __restrict__ out, int n) {
    int node = (blockIdx.x * blockDim.x + threadIdx.x) >> 5;
    int lane = threadIdx.x & 31;
    if (node >= n) return;
    int beg = __ldg(off + node);
    int end = beg + __ldg(cnt + node);
    float s = __ldg(dinv + node); s = s * s;

    float2 hv = *(const float2*)(h + (size_t)node * HID + lane * 2);
    float2 bv = __ldg((const float2*)b + lane);
    float2 acc;
    acc.x = bv.x + hv.x * s;
    acc.y = bv.y + hv.y * s;

    int j = beg;
    for (; j + 1 < end; j += 2) {
        int2 e0 = __ldg(csr + j);
        int2 e1 = __ldg(csr + j + 1);
        float w0 = __int_as_float(e0.y);
        float w1 = __int_as_float(e1.y);
        float2 v0 = __ldg((const float2*)(h + (size_t)e0.x * HID) + lane);
        float2 v1 = __ldg((const float2*)(h + (size_t)e1.x * HID) + lane);
        acc.x += v0.x * w0; acc.y += v0.y * w0;
        acc.x += v1.x * w1; acc.y += v1.y * w1;
    }
    if (j < end) {
        int2 e = __ldg(csr + j);
        float w = __int_as_float(e.y);
        float2 v = __ldg((const float2*)(h + (size_t)e.x * HID) + lane);
        acc.x += v.x * w; acc.y += v.y * w;
    }
    *(float2*)(out + (size_t)node * HID + lane * 2) = acc;
}

// ---------------------------------------------------------------- launch
extern "C" void kernel_launch(void* const* d_in, const int* in_sizes, int n_in,
                              void* d_out, int out_size) {
    const float* x  = (const float*)d_in[0];
    const int*   ei = (const int*)  d_in[1];
    const float* ew = (const float*)d_in[2];
    const float* W1 = (const float*)d_in[3];
    const float* b1 = (const float*)d_in[4];
    const float* W2 = (const float*)d_in[5];
    const float* b2 = (const float*)d_in[6];
    float* out = (float*)d_out;

    int n  = in_sizes[0] / HID;
    int ne = in_sizes[2];
    const int* src = ei;
    const int* dst = ei + ne;

    float *dinv, *h, *mid, *h2;
    int *cnt, *off, *cur, *bsum;
    int2 *csr;
    cudaGetSymbolAddress((void**)&dinv, g_dinv);
    cudaGetSymbolAddress((void**)&cnt,  g_cnt);
    cudaGetSymbolAddress((void**)&off,  g_off);
    cudaGetSymbolAddress((void**)&cur,  g_cur);
    cudaGetSymbolAddress((void**)&bsum, g_bsum);
    cudaGetSymbolAddress((void**)&csr,  g_csr);
    cudaGetSymbolAddress((void**)&h,    g_h);
    cudaGetSymbolAddress((void**)&mid,  g_mid);
    cudaGetSymbolAddress((void**)&h2,   g_h2);

    const int T = 256;
    int gn = (n + T - 1) / T;
    int ge = (ne + T - 1) / T;
    int nb = (n + 1023) / 1024;                       // scan blocks (98)
    int gg = (n + 63) / 64;                           // gemm blocks
    int gw = (int)(((size_t)n * 32 + T - 1) / T);     // gather blocks

    // CSR + normalization build (shared by both layers)
    k_init <<<gn, T>>>(dinv, cnt, n);
    k_hist <<<ge, T>>>(dst, ew, dinv, cnt, ne);
    k_dinv <<<gn, T>>>(dinv, n);
    k_scan1<<<nb, 1024>>>(cnt, off, bsum, n);
    k_scan2<<<1, 256>>>(bsum, nb);
    k_scan3<<<gn, T>>>(off, cur, bsum, n);
    k_place<<<ge, T>>>(src, dst, ew, dinv, cur, csr, ne);

    // layer 1
    k_gemm64<false><<<gg, 256>>>(x, W1, h, n);
    k_gather<<<gw, T>>>(h, csr, off, cnt, dinv, b1, mid, n);

    // layer 2 (relu fused into gemm load)
    k_gemm64<true><<<gg, 256>>>(mid, W2, h2, n);
    k_gather<<<gw, T>>>(h2, csr, off, cnt, dinv, b2, out, n);
}

// round 5
// speedup vs baseline: 1.5640x; 1.0567x over previous
#include <cuda_runtime.h>
#include <cuda_fp16.h>

#define NODES_MAX 100000
#define EDGES_MAX 1000000
#define HID 64

// Scratch (allocation-free rule: __device__ globals)
__device__ float  g_dinv[NODES_MAX];
__device__ int    g_cnt [NODES_MAX];
__device__ int    g_off [NODES_MAX];
__device__ int    g_cur [NODES_MAX];
__device__ int    g_bsum[256];
__device__ int2   g_csr [EDGES_MAX];
__device__ __half g_h  [(size_t)NODES_MAX * HID];   // fp16 projected features
__device__ float  g_mid[(size_t)NODES_MAX * HID];   // layer-1 output (fp32)

#define FMA_F32X2(d, a, b) \
    asm("fma.rn.f32x2 %0, %1, %2, %0;" : "+l"(d) : "l"(a), "l"(b))
#define PACK_F32X2(out, lo, hi) \
    asm("mov.b64 %0, {%1, %2};" : "=l"(out) : "f"(lo), "f"(hi))
#define UNPACK_F32X2(lo, hi, in) \
    asm("mov.b64 {%0, %1}, %2;" : "=f"(lo), "=f"(hi) : "l"(in))

// ---------------------------------------------------------------- prep
__global__ void k_init(float* deg, int* cnt, int n) {
    int i = blockIdx.x * blockDim.x + threadIdx.x;
    if (i < n) { deg[i] = 1.0f; cnt[i] = 0; }   // self-loop weight, zero hist
}

__global__ void k_hist(const int* __restrict__ dst, const float* __restrict__ ew,
                       float* deg, int* cnt, int ne) {
    int i = blockIdx.x * blockDim.x + threadIdx.x;
    if (i < ne) {
        int d = dst[i];
        atomicAdd(&deg[d], ew[i]);
        atomicAdd(&cnt[d], 1);
    }
}

// 3-kernel exclusive scan of cnt -> off
__global__ void k_scan1(const int* __restrict__ cnt, int* __restrict__ off,
                        int* __restrict__ bsum, int n) {
    __shared__ int ws[32];
    int i = blockIdx.x * 1024 + threadIdx.x;
    int lane = threadIdx.x & 31, w = threadIdx.x >> 5;
    int v = (i < n) ? cnt[i] : 0;
    int incl = v;
    #pragma unroll
    for (int d = 1; d < 32; d <<= 1) {
        int t = __shfl_up_sync(0xffffffffu, incl, d);
        if (lane >= d) incl += t;
    }
    if (lane == 31) ws[w] = incl;
    __syncthreads();
    if (w == 0) {
        int x = ws[lane];
        #pragma unroll
        for (int d = 1; d < 32; d <<= 1) {
            int t = __shfl_up_sync(0xffffffffu, x, d);
            if (lane >= d) x += t;
        }
        ws[lane] = x;
    }
    __syncthreads();
    int wpre = (w == 0) ? 0 : ws[w - 1];
    if (i < n) off[i] = wpre + incl - v;
    if (threadIdx.x == 1023) bsum[blockIdx.x] = ws[31];
}

__global__ void k_scan2(int* bsum, int nb) {
    __shared__ int s[256];
    int t = threadIdx.x;
    s[t] = (t < nb) ? bsum[t] : 0;
    __syncthreads();
    #pragma unroll
    for (int d = 1; d < 256; d <<= 1) {
        int v = (t >= d) ? s[t - d] : 0;
        __syncthreads();
        s[t] += v;
        __syncthreads();
    }
    if (t < nb) bsum[t] = (t == 0) ? 0 : s[t - 1];
}

// finish scan + compute dinv = rsqrt(deg)   (deg >= 1 always: self-loop)
__global__ void k_scan3(int* __restrict__ off, int* __restrict__ cur,
                        const int* __restrict__ bsum, float* deg, int n) {
    int i = blockIdx.x * blockDim.x + threadIdx.x;
    if (i < n) {
        int o = off[i] + bsum[i >> 10];
        off[i] = o;
        cur[i] = o;
        deg[i] = rsqrtf(deg[i]);
    }
}

// place edges: csr[pos] = {src, dinv[src]*ew*dinv[dst]}
__global__ void k_place(const int* __restrict__ src, const int* __restrict__ dst,
                        const float* __restrict__ ew, const float* __restrict__ dinv,
                        int* cur, int2* __restrict__ csr, int ne) {
    int i = blockIdx.x * blockDim.x + threadIdx.x;
    if (i < ne) {
        int s = src[i], d = dst[i];
        int pos = atomicAdd(&cur[d], 1);
        float w = __ldg(dinv + s) * ew[i] * __ldg(dinv + d);
        csr[pos] = make_int2(s, __float_as_int(w));
    }
}

// ---------------------------------------------------------------- GEMM
// Y[n,64] (fp16) = (RELU? max(X,0) : X) @ W[64,64]; 64 rows/block, 4x4 tile, f32x2 FMA
#define SX_STRIDE 68
template<bool RELU>
__global__ void __launch_bounds__(256) k_gemm64(const float* __restrict__ X,
                                                const float* __restrict__ W,
                                                __half* __restrict__ Y, int n) {
    __shared__ float sW[HID * HID];          // 16 KB
    __shared__ float sX[HID * SX_STRIDE];    // 17 KB (padded)
    int tid = threadIdx.x;
    int row0 = blockIdx.x * 64;

    #pragma unroll
    for (int j = 0; j < 4; j++) {
        int vi = tid + j * 256;              // float4 index 0..1023
        float4 wv = __ldg((const float4*)W + vi);
        *(float4*)&sW[vi * 4] = wv;
    }
    #pragma unroll
    for (int j = 0; j < 4; j++) {
        int vi = tid + j * 256;
        int r = vi >> 4;                     // 16 float4 per row
        int c4 = (vi & 15) * 4;
        float4 xv = make_float4(0.f, 0.f, 0.f, 0.f);
        if (row0 + r < n) xv = __ldg((const float4*)(X + (size_t)(row0 + r) * HID + c4));
        if (RELU) {
            xv.x = fmaxf(xv.x, 0.f); xv.y = fmaxf(xv.y, 0.f);
            xv.z = fmaxf(xv.z, 0.f); xv.w = fmaxf(xv.w, 0.f);
        }
        *(float4*)&sX[r * SX_STRIDE + c4] = xv;
    }
    __syncthreads();

    int tx = tid & 15, ty = tid >> 4;
    int c0 = tx * 4, r0 = ty * 4;
    unsigned long long acc[4][2];
    #pragma unroll
    for (int i = 0; i < 4; i++) { acc[i][0] = 0ull; acc[i][1] = 0ull; }

    #pragma unroll 4
    for (int k = 0; k < HID; k++) {
        float4 wv = *(const float4*)&sW[k * HID + c0];
        unsigned long long w01, w23;
        PACK_F32X2(w01, wv.x, wv.y);
        PACK_F32X2(w23, wv.z, wv.w);
        #pragma unroll
        for (int i = 0; i < 4; i++) {
            float x = sX[(r0 + i) * SX_STRIDE + k];
            unsigned long long xp;
            PACK_F32X2(xp, x, x);
            FMA_F32X2(acc[i][0], xp, w01);
            FMA_F32X2(acc[i][1], xp, w23);
        }
    }

    #pragma unroll
    for (int i = 0; i < 4; i++) {
        int r = row0 + r0 + i;
        if (r < n) {
            float4 o;
            UNPACK_F32X2(o.x, o.y, acc[i][0]);
            UNPACK_F32X2(o.z, o.w, acc[i][1]);
            __half2 p01 = __floats2half2_rn(o.x, o.y);
            __half2 p23 = __floats2half2_rn(o.z, o.w);
            uint2 pk;
            pk.x = *(unsigned int*)&p01;
            pk.y = *(unsigned int*)&p23;
            *(uint2*)(Y + (size_t)r * HID + c0) = pk;   // 8B store
        }
    }
}

// ---------------------------------------------------------------- gather
// out[i] = b + h[i]*dinv[i]^2 + sum_{edges into i} w * h[src]   (h in fp16)
__global__ void __launch_bounds__(256) k_gather(
    const __half* __restrict__ h, const int2* __restrict__ csr,
    const int* __restrict__ off, const int* __restrict__ cnt,
    const float* __restrict__ dinv, const float* __restrict__ b,
    float* __restrict__ out, int n) {
    int node = (blockIdx.x * blockDim.x + threadIdx.x) >> 5;
    int lane = threadIdx.x & 31;
    if (node >= n) return;
    int beg = __ldg(off + node);
    int deg = __ldg(cnt + node);
    int end = beg + deg;
    float s = __ldg(dinv + node); s = s * s;

    float2 hv = __half22float2(__ldg((const __half2*)(h + (size_t)node * HID) + lane));
    float2 bv = __ldg((const float2*)b + lane);
    float2 acc;
    acc.x = fmaf(hv.x, s, bv.x);
    acc.y = fmaf(hv.y, s, bv.y);

    int j = beg;
    int end4 = beg + (deg & ~3);
    for (; j < end4; j += 4) {
        int2 e0 = __ldg(csr + j);
        int2 e1 = __ldg(csr + j + 1);
        int2 e2 = __ldg(csr + j + 2);
        int2 e3 = __ldg(csr + j + 3);
        float2 v0 = __half22float2(__ldg((const __half2*)(h + (size_t)e0.x * HID) + lane));
        float2 v1 = __half22float2(__ldg((const __half2*)(h + (size_t)e1.x * HID) + lane));
        float2 v2 = __half22float2(__ldg((const __half2*)(h + (size_t)e2.x * HID) + lane));
        float2 v3 = __half22float2(__ldg((const __half2*)(h + (size_t)e3.x * HID) + lane));
        float w0 = __int_as_float(e0.y), w1 = __int_as_float(e1.y);
        float w2 = __int_as_float(e2.y), w3 = __int_as_float(e3.y);
        acc.x = fmaf(v0.x, w0, acc.x); acc.y = fmaf(v0.y, w0, acc.y);
        acc.x = fmaf(v1.x, w1, acc.x); acc.y = fmaf(v1.y, w1, acc.y);
        acc.x = fmaf(v2.x, w2, acc.x); acc.y = fmaf(v2.y, w2, acc.y);
        acc.x = fmaf(v3.x, w3, acc.x); acc.y = fmaf(v3.y, w3, acc.y);
    }
    for (; j < end; j++) {
        int2 e = __ldg(csr + j);
        float w = __int_as_float(e.y);
        float2 v = __half22float2(__ldg((const __half2*)(h + (size_t)e.x * HID) + lane));
        acc.x = fmaf(v.x, w, acc.x);
        acc.y = fmaf(v.y, w, acc.y);
    }
    *(float2*)(out + (size_t)node * HID + lane * 2) = acc;
}

// ---------------------------------------------------------------- launch
extern "C" void kernel_launch(void* const* d_in, const int* in_sizes, int n_in,
                              void* d_out, int out_size) {
    const float* x  = (const float*)d_in[0];
    const int*   ei = (const int*)  d_in[1];
    const float* ew = (const float*)d_in[2];
    const float* W1 = (const float*)d_in[3];
    const float* b1 = (const float*)d_in[4];
    const float* W2 = (const float*)d_in[5];
    const float* b2 = (const float*)d_in[6];
    float* out = (float*)d_out;

    int n  = in_sizes[0] / HID;
    int ne = in_sizes[2];
    const int* src = ei;
    const int* dst = ei + ne;

    float *dinv, *mid;
    __half *h;
    int *cnt, *off, *cur, *bsum;
    int2 *csr;
    cudaGetSymbolAddress((void**)&dinv, g_dinv);
    cudaGetSymbolAddress((void**)&cnt,  g_cnt);
    cudaGetSymbolAddress((void**)&off,  g_off);
    cudaGetSymbolAddress((void**)&cur,  g_cur);
    cudaGetSymbolAddress((void**)&bsum, g_bsum);
    cudaGetSymbolAddress((void**)&csr,  g_csr);
    cudaGetSymbolAddress((void**)&h,    g_h);
    cudaGetSymbolAddress((void**)&mid,  g_mid);

    const int T = 256;
    int gn = (n + T - 1) / T;
    int ge = (ne + T - 1) / T;
    int nb = (n + 1023) / 1024;                       // scan blocks (98)
    int gg = (n + 63) / 64;                           // gemm blocks
    int gw = (int)(((size_t)n * 32 + T - 1) / T);     // gather blocks

    // CSR + normalization build (shared by both layers)
    k_init <<<gn, T>>>(dinv, cnt, n);
    k_hist <<<ge, T>>>(dst, ew, dinv, cnt, ne);
    k_scan1<<<nb, 1024>>>(cnt, off, bsum, n);
    k_scan2<<<1, 256>>>(bsum, nb);
    k_scan3<<<gn, T>>>(off, cur, bsum, dinv, n);
    k_place<<<ge, T>>>(src, dst, ew, dinv, cur, csr, ne);

    // layer 1
    k_gemm64<false><<<gg, 256>>>(x, W1, h, n);
    k_gather<<<gw, T>>>(h, csr, off, cnt, dinv, b1, mid, n);

    // layer 2 (relu fused into gemm load)
    k_gemm64<true><<<gg, 256>>>(mid, W2, h, n);
    k_gather<<<gw, T>>>(h, csr, off, cnt, dinv, b2, out, n);
}

// round 8
// speedup vs baseline: 1.8057x; 1.1545x over previous
#include <cuda_runtime.h>
#include <cuda_fp16.h>

#define NODES_MAX 100000
#define EDGES_MAX 1000000
#define HID 64

// fixed-point scale for degree accumulation (packed with count in u64)
#define DEG_FX 67108864.0f           // 2^26
#define DEG_FX_INV (1.0f / 67108864.0f)
#define CNT_SHIFT 40
#define DEG_MASK ((1ull << CNT_SHIFT) - 1ull)

// Scratch (allocation-free rule: __device__ globals)
__device__ unsigned long long g_deg64[NODES_MAX];
__device__ float  g_dinv[NODES_MAX];
__device__ int    g_cnt [NODES_MAX];
__device__ int    g_off [NODES_MAX];
__device__ int    g_cur [NODES_MAX];
__device__ int    g_bsum[256];
__device__ int2   g_csr [EDGES_MAX];
__device__ __half g_h  [(size_t)NODES_MAX * HID];   // fp16 projected features
__device__ float  g_mid[(size_t)NODES_MAX * HID];   // layer-1 output (fp32)

#define FMA_F32X2(d, a, b) \
    asm("fma.rn.f32x2 %0, %1, %2, %0;" : "+l"(d) : "l"(a), "l"(b))
#define PACK_F32X2(out, lo, hi) \
    asm("mov.b64 %0, {%1, %2};" : "=l"(out) : "f"(lo), "f"(hi))
#define UNPACK_F32X2(lo, hi, in) \
    asm("mov.b64 {%0, %1}, %2;" : "=f"(lo), "=f"(hi) : "l"(in))

// ---------------------------------------------------------------- prep
__global__ void k_init(unsigned long long* deg64, int n) {
    int i = blockIdx.x * blockDim.x + threadIdx.x;
    if (i < n) deg64[i] = (unsigned long long)(1.0f * DEG_FX);  // self-loop, cnt=0
}

// one u64 atomic per edge: count in high bits, fixed-point ew sum in low bits
__global__ void k_hist(const int* __restrict__ dst, const float* __restrict__ ew,
                       unsigned long long* deg64, int ne) {
    int i = blockIdx.x * blockDim.x + threadIdx.x;
    if (i < ne) {
        unsigned long long v = (1ull << CNT_SHIFT)
                             + (unsigned long long)__float2ull_rn(ew[i] * DEG_FX);
        atomicAdd(&deg64[dst[i]], v);
    }
}

// 3-kernel exclusive scan of counts (extracted from deg64) -> off; also writes cnt
__global__ void k_scan1(const unsigned long long* __restrict__ deg64,
                        int* __restrict__ cnt, int* __restrict__ off,
                        int* __restrict__ bsum, int n) {
    __shared__ int ws[32];
    int i = blockIdx.x * 1024 + threadIdx.x;
    int lane = threadIdx.x & 31, w = threadIdx.x >> 5;
    int v = (i < n) ? (int)(__ldg(deg64 + i) >> CNT_SHIFT) : 0;
    if (i < n) cnt[i] = v;
    int incl = v;
    #pragma unroll
    for (int d = 1; d < 32; d <<= 1) {
        int t = __shfl_up_sync(0xffffffffu, incl, d);
        if (lane >= d) incl += t;
    }
    if (lane == 31) ws[w] = incl;
    __syncthreads();
    if (w == 0) {
        int x = ws[lane];
        #pragma unroll
        for (int d = 1; d < 32; d <<= 1) {
            int t = __shfl_up_sync(0xffffffffu, x, d);
            if (lane >= d) x += t;
        }
        ws[lane] = x;
    }
    __syncthreads();
    int wpre = (w == 0) ? 0 : ws[w - 1];
    if (i < n) off[i] = wpre + incl - v;
    if (threadIdx.x == 1023) bsum[blockIdx.x] = ws[31];
}

__global__ void k_scan2(int* bsum, int nb) {
    __shared__ int s[256];
    int t = threadIdx.x;
    s[t] = (t < nb) ? bsum[t] : 0;
    __syncthreads();
    #pragma unroll
    for (int d = 1; d < 256; d <<= 1) {
        int v = (t >= d) ? s[t - d] : 0;
        __syncthreads();
        s[t] += v;
        __syncthreads();
    }
    if (t < nb) bsum[t] = (t == 0) ? 0 : s[t - 1];
}

// finish scan + compute dinv = rsqrt(deg)   (deg >= 1 always: self-loop)
__global__ void k_scan3(int* __restrict__ off, int* __restrict__ cur,
                        const int* __restrict__ bsum,
                        const unsigned long long* __restrict__ deg64,
                        float* __restrict__ dinv, int n) {
    int i = blockIdx.x * blockDim.x + threadIdx.x;
    if (i < n) {
        int o = off[i] + bsum[i >> 10];
        off[i] = o;
        cur[i] = o;
        float d = (float)(__ldg(deg64 + i) & DEG_MASK) * DEG_FX_INV;
        dinv[i] = rsqrtf(d);
    }
}

// place edges: csr[pos] = {src, dinv[src]*ew*dinv[dst]}
__global__ void k_place(const int* __restrict__ src, const int* __restrict__ dst,
                        const float* __restrict__ ew, const float* __restrict__ dinv,
                        int* cur, int2* __restrict__ csr, int ne) {
    int i = blockIdx.x * blockDim.x + threadIdx.x;
    if (i < ne) {
        int s = src[i], d = dst[i];
        int pos = atomicAdd(&cur[d], 1);
        float w = __ldg(dinv + s) * ew[i] * __ldg(dinv + d);
        csr[pos] = make_int2(s, __float_as_int(w));
    }
}

// ---------------------------------------------------------------- GEMM
// Y[n,64] (fp16) = (RELU? max(X,0) : X) @ W[64,64]; 64 rows/block, 4x4 tile, f32x2 FMA
#define SX_STRIDE 68
template<bool RELU>
__global__ void __launch_bounds__(256) k_gemm64(const float* __restrict__ X,
                                                const float* __restrict__ W,
                                                __half* __restrict__ Y, int n) {
    __shared__ float sW[HID * HID];          // 16 KB
    __shared__ float sX[HID * SX_STRIDE];    // 17 KB (padded)
    int tid = threadIdx.x;
    int row0 = blockIdx.x * 64;

    #pragma unroll
    for (int j = 0; j < 4; j++) {
        int vi = tid + j * 256;              // float4 index 0..1023
        float4 wv = __ldg((const float4*)W + vi);
        *(float4*)&sW[vi * 4] = wv;
    }
    #pragma unroll
    for (int j = 0; j < 4; j++) {
        int vi = tid + j * 256;
        int r = vi >> 4;                     // 16 float4 per row
        int c4 = (vi & 15) * 4;
        float4 xv = make_float4(0.f, 0.f, 0.f, 0.f);
        if (row0 + r < n) xv = __ldg((const float4*)(X + (size_t)(row0 + r) * HID + c4));
        if (RELU) {
            xv.x = fmaxf(xv.x, 0.f); xv.y = fmaxf(xv.y, 0.f);
            xv.z = fmaxf(xv.z, 0.f); xv.w = fmaxf(xv.w, 0.f);
        }
        *(float4*)&sX[r * SX_STRIDE + c4] = xv;
    }
    __syncthreads();

    int tx = tid & 15, ty = tid >> 4;
    int c0 = tx * 4, r0 = ty * 4;
    unsigned long long acc[4][2];
    #pragma unroll
    for (int i = 0; i < 4; i++) { acc[i][0] = 0ull; acc[i][1] = 0ull; }

    #pragma unroll 4
    for (int k = 0; k < HID; k++) {
        float4 wv = *(const float4*)&sW[k * HID + c0];
        unsigned long long w01, w23;
        PACK_F32X2(w01, wv.x, wv.y);
        PACK_F32X2(w23, wv.z, wv.w);
        #pragma unroll
        for (int i = 0; i < 4; i++) {
            float x = sX[(r0 + i) * SX_STRIDE + k];
            unsigned long long xp;
            PACK_F32X2(xp, x, x);
            FMA_F32X2(acc[i][0], xp, w01);
            FMA_F32X2(acc[i][1], xp, w23);
        }
    }

    #pragma unroll
    for (int i = 0; i < 4; i++) {
        int r = row0 + r0 + i;
        if (r < n) {
            float4 o;
            UNPACK_F32X2(o.x, o.y, acc[i][0]);
            UNPACK_F32X2(o.z, o.w, acc[i][1]);
            __half2 p01 = __floats2half2_rn(o.x, o.y);
            __half2 p23 = __floats2half2_rn(o.z, o.w);
            uint2 pk;
            pk.x = *(unsigned int*)&p01;
            pk.y = *(unsigned int*)&p23;
            *(uint2*)(Y + (size_t)r * HID + c0) = pk;   // 8B store
        }
    }
}

// ---------------------------------------------------------------- gather
// out[i] = b + h[i]*dinv[i]^2 + sum_{edges into i} w * h[src]   (h in fp16)
// 8 lanes per node (4 nodes per warp): each lane loads uint4 = 8 halves = 16B.
// One LDG.128 serves 4 independent edge chains -> 4x MLP per load instruction.
__global__ void __launch_bounds__(256) k_gather(
    const __half* __restrict__ h, const int2* __restrict__ csr,
    const int* __restrict__ off, const int* __restrict__ cnt,
    const float* __restrict__ dinv, const float* __restrict__ b,
    float* __restrict__ out, int n) {
    int gtid = blockIdx.x * blockDim.x + threadIdx.x;
    int node = gtid >> 3;
    int gl   = gtid & 7;
    if (node >= n) return;
    int beg = __ldg(off + node);
    int deg = __ldg(cnt + node);
    float s = __ldg(dinv + node); s = s * s;

    float acc[8];
    {   // self-loop + bias
        uint4 hp = __ldg((const uint4*)(h + (size_t)node * HID) + gl);
        float2 f0 = __half22float2(*(__half2*)&hp.x);
        float2 f1 = __half22float2(*(__half2*)&hp.y);
        float2 f2 = __half22float2(*(__half2*)&hp.z);
        float2 f3 = __half22float2(*(__half2*)&hp.w);
        float4 bv0 = __ldg((const float4*)b + gl * 2);
        float4 bv1 = __ldg((const float4*)b + gl * 2 + 1);
        acc[0] = fmaf(f0.x, s, bv0.x); acc[1] = fmaf(f0.y, s, bv0.y);
        acc[2] = fmaf(f1.x, s, bv0.z); acc[3] = fmaf(f1.y, s, bv0.w);
        acc[4] = fmaf(f2.x, s, bv1.x); acc[5] = fmaf(f2.y, s, bv1.y);
        acc[6] = fmaf(f3.x, s, bv1.z); acc[7] = fmaf(f3.y, s, bv1.w);
    }

    int j = beg, end = beg + deg, end2 = beg + (deg & ~1);
    for (; j < end2; j += 2) {
        int2 e0 = __ldg(csr + j);
        int2 e1 = __ldg(csr + j + 1);
        uint4 p0 = __ldg((const uint4*)(h + (size_t)e0.x * HID) + gl);
        uint4 p1 = __ldg((const uint4*)(h + (size_t)e1.x * HID) + gl);
        float w0 = __int_as_float(e0.y);
        float w1 = __int_as_float(e1.y);
        float2 a0 = __half22float2(*(__half2*)&p0.x);
        float2 a1 = __half22float2(*(__half2*)&p0.y);
        float2 a2 = __half22float2(*(__half2*)&p0.z);
        float2 a3 = __half22float2(*(__half2*)&p0.w);
        acc[0] = fmaf(a0.x, w0, acc[0]); acc[1] = fmaf(a0.y, w0, acc[1]);
        acc[2] = fmaf(a1.x, w0, acc[2]); acc[3] = fmaf(a1.y, w0, acc[3]);
        acc[4] = fmaf(a2.x, w0, acc[4]); acc[5] = fmaf(a2.y, w0, acc[5]);
        acc[6] = fmaf(a3.x, w0, acc[6]); acc[7] = fmaf(a3.y, w0, acc[7]);
        float2 c0 = __half22float2(*(__half2*)&p1.x);
        float2 c1 = __half22float2(*(__half2*)&p1.y);
        float2 c2 = __half22float2(*(__half2*)&p1.z);
        float2 c3 = __half22float2(*(__half2*)&p1.w);
        acc[0] = fmaf(c0.x, w1, acc[0]); acc[1] = fmaf(c0.y, w1, acc[1]);
        acc[2] = fmaf(c1.x, w1, acc[2]); acc[3] = fmaf(c1.y, w1, acc[3]);
        acc[4] = fmaf(c2.x, w1, acc[4]); acc[5] = fmaf(c2.y, w1, acc[5]);
        acc[6] = fmaf(c3.x, w1, acc[6]); acc[7] = fmaf(c3.y, w1, acc[7]);
    }
    if (j < end) {
        int2 e = __ldg(csr + j);
        uint4 p = __ldg((const uint4*)(h + (size_t)e.x * HID) + gl);
        float w = __int_as_float(e.y);
        float2 a0 = __half22float2(*(__half2*)&p.x);
        float2 a1 = __half22float2(*(__half2*)&p.y);
        float2 a2 = __half22float2(*(__half2*)&p.z);
        float2 a3 = __half22float2(*(__half2*)&p.w);
        acc[0] = fmaf(a0.x, w, acc[0]); acc[1] = fmaf(a0.y, w, acc[1]);
        acc[2] = fmaf(a1.x, w, acc[2]); acc[3] = fmaf(a1.y, w, acc[3]);
        acc[4] = fmaf(a2.x, w, acc[4]); acc[5] = fmaf(a2.y, w, acc[5]);
        acc[6] = fmaf(a3.x, w, acc[6]); acc[7] = fmaf(a3.y, w, acc[7]);
    }

    float* op = out + (size_t)node * HID + gl * 8;
    *(float4*)op       = make_float4(acc[0], acc[1], acc[2], acc[3]);
    *(float4*)(op + 4) = make_float4(acc[4], acc[5], acc[6], acc[7]);
}

// ---------------------------------------------------------------- launch
extern "C" void kernel_launch(void* const* d_in, const int* in_sizes, int n_in,
                              void* d_out, int out_size) {
    const float* x  = (const float*)d_in[0];
    const int*   ei = (const int*)  d_in[1];
    const float* ew = (const float*)d_in[2];
    const float* W1 = (const float*)d_in[3];
    const float* b1 = (const float*)d_in[4];
    const float* W2 = (const float*)d_in[5];
    const float* b2 = (const float*)d_in[6];
    float* out = (float*)d_out;

    int n  = in_sizes[0] / HID;
    int ne = in_sizes[2];
    const int* src = ei;
    const int* dst = ei + ne;

    unsigned long long* deg64;
    float *dinv, *mid;
    __half *h;
    int *cnt, *off, *cur, *bsum;
    int2 *csr;
    cudaGetSymbolAddress((void**)&deg64, g_deg64);
    cudaGetSymbolAddress((void**)&dinv, g_dinv);
    cudaGetSymbolAddress((void**)&cnt,  g_cnt);
    cudaGetSymbolAddress((void**)&off,  g_off);
    cudaGetSymbolAddress((void**)&cur,  g_cur);
    cudaGetSymbolAddress((void**)&bsum, g_bsum);
    cudaGetSymbolAddress((void**)&csr,  g_csr);
    cudaGetSymbolAddress((void**)&h,    g_h);
    cudaGetSymbolAddress((void**)&mid,  g_mid);

    const int T = 256;
    int gn = (n + T - 1) / T;
    int ge = (ne + T - 1) / T;
    int nb = (n + 1023) / 1024;                       // scan blocks (98)
    int gg = (n + 63) / 64;                           // gemm blocks
    int gw = (int)(((size_t)n * 8 + T - 1) / T);      // gather blocks (8 lanes/node)

    // CSR + normalization build (shared by both layers)
    k_init <<<gn, T>>>(deg64, n);
    k_hist <<<ge, T>>>(dst, ew, deg64, ne);
    k_scan1<<<nb, 1024>>>(deg64, cnt, off, bsum, n);
    k_scan2<<<1, 256>>>(bsum, nb);
    k_scan3<<<gn, T>>>(off, cur, bsum, deg64, dinv, n);
    k_place<<<ge, T>>>(src, dst, ew, dinv, cur, csr, ne);

    // layer 1
    k_gemm64<false><<<gg, 256>>>(x, W1, h, n);
    k_gather<<<gw, T>>>(h, csr, off, cnt, dinv, b1, mid, n);

    // layer 2 (relu fused into gemm load)
    k_gemm64<true><<<gg, 256>>>(mid, W2, h, n);
    k_gather<<<gw, T>>>(h, csr, off, cnt, dinv, b2, out, n);
}

// round 9
// speedup vs baseline: 1.8126x; 1.0038x over previous
#include <cuda_runtime.h>
#include <cuda_fp16.h>

#define NODES_MAX 100000
#define EDGES_MAX 1000000
#define HID 64

// fixed-point scale for degree accumulation (packed with count in u64)
#define DEG_FX 67108864.0f           // 2^26
#define DEG_FX_INV (1.0f / 67108864.0f)
#define CNT_SHIFT 40
#define DEG_MASK ((1ull << CNT_SHIFT) - 1ull)

// Scratch (allocation-free rule: __device__ globals)
__device__ unsigned long long g_deg64[NODES_MAX];
__device__ float  g_dinv[NODES_MAX];
__device__ int    g_cnt [NODES_MAX];
__device__ int    g_off [NODES_MAX];
__device__ int    g_cur [NODES_MAX];
__device__ int    g_bsum[256];
__device__ int2   g_csr [EDGES_MAX];
__device__ __half g_h  [(size_t)NODES_MAX * HID];   // fp16 projected features
__device__ float  g_mid[(size_t)NODES_MAX * HID];   // layer-1 output (fp32)

#define FMA_F32X2(d, a, b) \
    asm("fma.rn.f32x2 %0, %1, %2, %0;" : "+l"(d) : "l"(a), "l"(b))
#define PACK_F32X2(out, lo, hi) \
    asm("mov.b64 %0, {%1, %2};" : "=l"(out) : "f"(lo), "f"(hi))
#define UNPACK_F32X2(lo, hi, in) \
    asm("mov.b64 {%0, %1}, %2;" : "=f"(lo), "=f"(hi) : "l"(in))

// ---------------------------------------------------------------- prep
__global__ void k_init(unsigned long long* deg64, int n) {
    int i = blockIdx.x * blockDim.x + threadIdx.x;
    if (i < n) deg64[i] = (unsigned long long)(1.0f * DEG_FX);  // self-loop, cnt=0
}

// one u64 atomic per edge: count in high bits, fixed-point ew sum in low bits
__global__ void k_hist(const int* __restrict__ dst, const float* __restrict__ ew,
                       unsigned long long* deg64, int ne) {
    int i = blockIdx.x * blockDim.x + threadIdx.x;
    if (i < ne) {
        unsigned long long v = (1ull << CNT_SHIFT)
                             + (unsigned long long)__float2ull_rn(ew[i] * DEG_FX);
        atomicAdd(&deg64[dst[i]], v);
    }
}

// 3-kernel exclusive scan of counts (extracted from deg64) -> off; also writes cnt
__global__ void k_scan1(const unsigned long long* __restrict__ deg64,
                        int* __restrict__ cnt, int* __restrict__ off,
                        int* __restrict__ bsum, int n) {
    __shared__ int ws[32];
    int i = blockIdx.x * 1024 + threadIdx.x;
    int lane = threadIdx.x & 31, w = threadIdx.x >> 5;
    int v = (i < n) ? (int)(__ldg(deg64 + i) >> CNT_SHIFT) : 0;
    if (i < n) cnt[i] = v;
    int incl = v;
    #pragma unroll
    for (int d = 1; d < 32; d <<= 1) {
        int t = __shfl_up_sync(0xffffffffu, incl, d);
        if (lane >= d) incl += t;
    }
    if (lane == 31) ws[w] = incl;
    __syncthreads();
    if (w == 0) {
        int x = ws[lane];
        #pragma unroll
        for (int d = 1; d < 32; d <<= 1) {
            int t = __shfl_up_sync(0xffffffffu, x, d);
            if (lane >= d) x += t;
        }
        ws[lane] = x;
    }
    __syncthreads();
    int wpre = (w == 0) ? 0 : ws[w - 1];
    if (i < n) off[i] = wpre + incl - v;
    if (threadIdx.x == 1023) bsum[blockIdx.x] = ws[31];
}

__global__ void k_scan2(int* bsum, int nb) {
    __shared__ int s[256];
    int t = threadIdx.x;
    s[t] = (t < nb) ? bsum[t] : 0;
    __syncthreads();
    #pragma unroll
    for (int d = 1; d < 256; d <<= 1) {
        int v = (t >= d) ? s[t - d] : 0;
        __syncthreads();
        s[t] += v;
        __syncthreads();
    }
    if (t < nb) bsum[t] = (t == 0) ? 0 : s[t - 1];
}

// finish scan + compute dinv = rsqrt(deg)   (deg >= 1 always: self-loop)
__global__ void k_scan3(int* __restrict__ off, int* __restrict__ cur,
                        const int* __restrict__ bsum,
                        const unsigned long long* __restrict__ deg64,
                        float* __restrict__ dinv, int n) {
    int i = blockIdx.x * blockDim.x + threadIdx.x;
    if (i < n) {
        int o = off[i] + bsum[i >> 10];
        off[i] = o;
        cur[i] = o;
        float d = (float)(__ldg(deg64 + i) & DEG_MASK) * DEG_FX_INV;
        dinv[i] = rsqrtf(d);
    }
}

// place edges: csr[pos] = {src, dinv[src]*ew*dinv[dst]}
__global__ void k_place(const int* __restrict__ src, const int* __restrict__ dst,
                        const float* __restrict__ ew, const float* __restrict__ dinv,
                        int* cur, int2* __restrict__ csr, int ne) {
    int i = blockIdx.x * blockDim.x + threadIdx.x;
    if (i < ne) {
        int s = src[i], d = dst[i];
        int pos = atomicAdd(&cur[d], 1);
        float w = __ldg(dinv + s) * ew[i] * __ldg(dinv + d);
        csr[pos] = make_int2(s, __float_as_int(w));
    }
}

// ---------------------------------------------------------------- GEMM
// Y[n,64] (fp16) = (RELU? max(X,0) : X) @ W[64,64]; 64 rows/block, 4x4 tile, f32x2 FMA
#define SX_STRIDE 68
template<bool RELU>
__global__ void __launch_bounds__(256) k_gemm64(const float* __restrict__ X,
                                                const float* __restrict__ W,
                                                __half* __restrict__ Y, int n) {
    __shared__ float sW[HID * HID];          // 16 KB
    __shared__ float sX[HID * SX_STRIDE];    // 17 KB (padded)
    int tid = threadIdx.x;
    int row0 = blockIdx.x * 64;

    #pragma unroll
    for (int j = 0; j < 4; j++) {
        int vi = tid + j * 256;              // float4 index 0..1023
        float4 wv = __ldg((const float4*)W + vi);
        *(float4*)&sW[vi * 4] = wv;
    }
    #pragma unroll
    for (int j = 0; j < 4; j++) {
        int vi = tid + j * 256;
        int r = vi >> 4;                     // 16 float4 per row
        int c4 = (vi & 15) * 4;
        float4 xv = make_float4(0.f, 0.f, 0.f, 0.f);
        if (row0 + r < n) xv = __ldg((const float4*)(X + (size_t)(row0 + r) * HID + c4));
        if (RELU) {
            xv.x = fmaxf(xv.x, 0.f); xv.y = fmaxf(xv.y, 0.f);
            xv.z = fmaxf(xv.z, 0.f); xv.w = fmaxf(xv.w, 0.f);
        }
        *(float4*)&sX[r * SX_STRIDE + c4] = xv;
    }
    __syncthreads();

    int tx = tid & 15, ty = tid >> 4;
    int c0 = tx * 4, r0 = ty * 4;
    unsigned long long acc[4][2];
    #pragma unroll
    for (int i = 0; i < 4; i++) { acc[i][0] = 0ull; acc[i][1] = 0ull; }

    #pragma unroll 4
    for (int k = 0; k < HID; k++) {
        float4 wv = *(const float4*)&sW[k * HID + c0];
        unsigned long long w01, w23;
        PACK_F32X2(w01, wv.x, wv.y);
        PACK_F32X2(w23, wv.z, wv.w);
        #pragma unroll
        for (int i = 0; i < 4; i++) {
            float x = sX[(r0 + i) * SX_STRIDE + k];
            unsigned long long xp;
            PACK_F32X2(xp, x, x);
            FMA_F32X2(acc[i][0], xp, w01);
            FMA_F32X2(acc[i][1], xp, w23);
        }
    }

    #pragma unroll
    for (int i = 0; i < 4; i++) {
        int r = row0 + r0 + i;
        if (r < n) {
            float4 o;
            UNPACK_F32X2(o.x, o.y, acc[i][0]);
            UNPACK_F32X2(o.z, o.w, acc[i][1]);
            __half2 p01 = __floats2half2_rn(o.x, o.y);
            __half2 p23 = __floats2half2_rn(o.z, o.w);
            uint2 pk;
            pk.x = *(unsigned int*)&p01;
            pk.y = *(unsigned int*)&p23;
            *(uint2*)(Y + (size_t)r * HID + c0) = pk;   // 8B store
        }
    }
}

// ---------------------------------------------------------------- gather
// out[i] = b + h[i]*dinv[i]^2 + sum_{edges into i} w * h[src]   (h in fp16)
// 8 lanes per node (4 nodes per warp): each lane loads uint4 = 8 halves = 16B.
// One LDG.128 serves 4 independent edge chains -> 4x MLP per load instruction.
__global__ void __launch_bounds__(256) k_gather(
    const __half* __restrict__ h, const int2* __restrict__ csr,
    const int* __restrict__ off, const int* __restrict__ cnt,
    const float* __restrict__ dinv, const float* __restrict__ b,
    float* __restrict__ out, int n) {
    int gtid = blockIdx.x * blockDim.x + threadIdx.x;
    int node = gtid >> 3;
    int gl   = gtid & 7;
    if (node >= n) return;
    int beg = __ldg(off + node);
    int deg = __ldg(cnt + node);
    float s = __ldg(dinv + node); s = s * s;

    float acc[8];
    {   // self-loop + bias
        uint4 hp = __ldg((const uint4*)(h + (size_t)node * HID) + gl);
        float2 f0 = __half22float2(*(__half2*)&hp.x);
        float2 f1 = __half22float2(*(__half2*)&hp.y);
        float2 f2 = __half22float2(*(__half2*)&hp.z);
        float2 f3 = __half22float2(*(__half2*)&hp.w);
        float4 bv0 = __ldg((const float4*)b + gl * 2);
        float4 bv1 = __ldg((const float4*)b + gl * 2 + 1);
        acc[0] = fmaf(f0.x, s, bv0.x); acc[1] = fmaf(f0.y, s, bv0.y);
        acc[2] = fmaf(f1.x, s, bv0.z); acc[3] = fmaf(f1.y, s, bv0.w);
        acc[4] = fmaf(f2.x, s, bv1.x); acc[5] = fmaf(f2.y, s, bv1.y);
        acc[6] = fmaf(f3.x, s, bv1.z); acc[7] = fmaf(f3.y, s, bv1.w);
    }

    int j = beg, end = beg + deg, end2 = beg + (deg & ~1);
    for (; j < end2; j += 2) {
        int2 e0 = __ldg(csr + j);
        int2 e1 = __ldg(csr + j + 1);
        uint4 p0 = __ldg((const uint4*)(h + (size_t)e0.x * HID) + gl);
        uint4 p1 = __ldg((const uint4*)(h + (size_t)e1.x * HID) + gl);
        float w0 = __int_as_float(e0.y);
        float w1 = __int_as_float(e1.y);
        float2 a0 = __half22float2(*(__half2*)&p0.x);
        float2 a1 = __half22float2(*(__half2*)&p0.y);
        float2 a2 = __half22float2(*(__half2*)&p0.z);
        float2 a3 = __half22float2(*(__half2*)&p0.w);
        acc[0] = fmaf(a0.x, w0, acc[0]); acc[1] = fmaf(a0.y, w0, acc[1]);
        acc[2] = fmaf(a1.x, w0, acc[2]); acc[3] = fmaf(a1.y, w0, acc[3]);
        acc[4] = fmaf(a2.x, w0, acc[4]); acc[5] = fmaf(a2.y, w0, acc[5]);
        acc[6] = fmaf(a3.x, w0, acc[6]); acc[7] = fmaf(a3.y, w0, acc[7]);
        float2 c0 = __half22float2(*(__half2*)&p1.x);
        float2 c1 = __half22float2(*(__half2*)&p1.y);
        float2 c2 = __half22float2(*(__half2*)&p1.z);
        float2 c3 = __half22float2(*(__half2*)&p1.w);
        acc[0] = fmaf(c0.x, w1, acc[0]); acc[1] = fmaf(c0.y, w1, acc[1]);
        acc[2] = fmaf(c1.x, w1, acc[2]); acc[3] = fmaf(c1.y, w1, acc[3]);
        acc[4] = fmaf(c2.x, w1, acc[4]); acc[5] = fmaf(c2.y, w1, acc[5]);
        acc[6] = fmaf(c3.x, w1, acc[6]); acc[7] = fmaf(c3.y, w1, acc[7]);
    }
    if (j < end) {
        int2 e = __ldg(csr + j);
        uint4 p = __ldg((const uint4*)(h + (size_t)e.x * HID) + gl);
        float w = __int_as_float(e.y);
        float2 a0 = __half22float2(*(__half2*)&p.x);
        float2 a1 = __half22float2(*(__half2*)&p.y);
        float2 a2 = __half22float2(*(__half2*)&p.z);
        float2 a3 = __half22float2(*(__half2*)&p.w);
        acc[0] = fmaf(a0.x, w, acc[0]); acc[1] = fmaf(a0.y, w, acc[1]);
        acc[2] = fmaf(a1.x, w, acc[2]); acc[3] = fmaf(a1.y, w, acc[3]);
        acc[4] = fmaf(a2.x, w, acc[4]); acc[5] = fmaf(a2.y, w, acc[5]);
        acc[6] = fmaf(a3.x, w, acc[6]); acc[7] = fmaf(a3.y, w, acc[7]);
    }

    float* op = out + (size_t)node * HID + gl * 8;
    *(float4*)op       = make_float4(acc[0], acc[1], acc[2], acc[3]);
    *(float4*)(op + 4) = make_float4(acc[4], acc[5], acc[6], acc[7]);
}

// ---------------------------------------------------------------- launch
extern "C" void kernel_launch(void* const* d_in, const int* in_sizes, int n_in,
                              void* d_out, int out_size) {
    const float* x  = (const float*)d_in[0];
    const int*   ei = (const int*)  d_in[1];
    const float* ew = (const float*)d_in[2];
    const float* W1 = (const float*)d_in[3];
    const float* b1 = (const float*)d_in[4];
    const float* W2 = (const float*)d_in[5];
    const float* b2 = (const float*)d_in[6];
    float* out = (float*)d_out;

    int n  = in_sizes[0] / HID;
    int ne = in_sizes[2];
    const int* src = ei;
    const int* dst = ei + ne;

    unsigned long long* deg64;
    float *dinv, *mid;
    __half *h;
    int *cnt, *off, *cur, *bsum;
    int2 *csr;
    cudaGetSymbolAddress((void**)&deg64, g_deg64);
    cudaGetSymbolAddress((void**)&dinv, g_dinv);
    cudaGetSymbolAddress((void**)&cnt,  g_cnt);
    cudaGetSymbolAddress((void**)&off,  g_off);
    cudaGetSymbolAddress((void**)&cur,  g_cur);
    cudaGetSymbolAddress((void**)&bsum, g_bsum);
    cudaGetSymbolAddress((void**)&csr,  g_csr);
    cudaGetSymbolAddress((void**)&h,    g_h);
    cudaGetSymbolAddress((void**)&mid,  g_mid);

    const int T = 256;
    int gn = (n + T - 1) / T;
    int ge = (ne + T - 1) / T;
    int nb = (n + 1023) / 1024;                       // scan blocks (98)
    int gg = (n + 63) / 64;                           // gemm blocks
    int gw = (int)(((size_t)n * 8 + T - 1) / T);      // gather blocks (8 lanes/node)

    // CSR + normalization build (shared by both layers)
    k_init <<<gn, T>>>(deg64, n);
    k_hist <<<ge, T>>>(dst, ew, deg64, ne);
    k_scan1<<<nb, 1024>>>(deg64, cnt, off, bsum, n);
    k_scan2<<<1, 256>>>(bsum, nb);
    k_scan3<<<gn, T>>>(off, cur, bsum, deg64, dinv, n);
    k_place<<<ge, T>>>(src, dst, ew, dinv, cur, csr, ne);

    // layer 1
    k_gemm64<false><<<gg, 256>>>(x, W1, h, n);
    k_gather<<<gw, T>>>(h, csr, off, cnt, dinv, b1, mid, n);

    // layer 2 (relu fused into gemm load)
    k_gemm64<true><<<gg, 256>>>(mid, W2, h, n);
    k_gather<<<gw, T>>>(h, csr, off, cnt, dinv, b2, out, n);
}